// round 1
// baseline (speedup 1.0000x reference)
#include <cuda_runtime.h>
#include <cuda_bf16.h>

// Problem: B=32, C=512, H=W=64
//   d[b,c] = max over HW, e[b,c] = mean over HW
//   y[b,i,j] = softmax_j( d_i*d_j + e_i*e_j )
//   f[b,j]   = alpha * sum_i d_i*y[i,j] + beta * sum_i e_i*y[i,j]
//   out[b,c,h,w] = f[b,c]
//
// Phase 1: pool (read 268 MB)            -> HBM bound
// Phase 2: row sums s_i, store a=d/s,b=e/s (tiny)
// Phase 3: col sums -> f (tiny; uses l_ij symmetry, no max-subtract needed:
//          |logit| <= d_max^2 ~ 18 << 88, exp stays finite in fp32)
// Phase 4: broadcast (write 268 MB)      -> HBM bound

#define BATCH 32
#define CH    512
#define HW    4096
#define BC    (BATCH * CH)

__device__ float  g_d[BC];
__device__ float  g_e[BC];
__device__ float2 g_ab[BC];   // (d_i/s_i, e_i/s_i)
__device__ float  g_f[BC];

// ---------------------------------------------------------------------------
// Kernel 1: per-(b,c) max + mean over 4096 contiguous floats.
// One block of 256 threads per (b,c); each thread loads 4 x float4.
// ---------------------------------------------------------------------------
__global__ void pool_kernel(const float4* __restrict__ x) {
    const int bc = blockIdx.x;
    const float4* p = x + (size_t)bc * (HW / 4);
    const int t = threadIdx.x;

    float mx = -3.402823466e38f;
    float sm = 0.0f;
#pragma unroll
    for (int k = 0; k < 4; ++k) {
        float4 v = p[t + k * 256];
        mx = fmaxf(mx, fmaxf(fmaxf(v.x, v.y), fmaxf(v.z, v.w)));
        sm += (v.x + v.y) + (v.z + v.w);
    }
#pragma unroll
    for (int o = 16; o > 0; o >>= 1) {
        mx = fmaxf(mx, __shfl_xor_sync(0xFFFFFFFFu, mx, o));
        sm += __shfl_xor_sync(0xFFFFFFFFu, sm, o);
    }
    __shared__ float smx[8];
    __shared__ float ssm[8];
    const int w = t >> 5;
    if ((t & 31) == 0) { smx[w] = mx; ssm[w] = sm; }
    __syncthreads();
    if (t < 8) {
        mx = smx[t];
        sm = ssm[t];
#pragma unroll
        for (int o = 4; o > 0; o >>= 1) {
            mx = fmaxf(mx, __shfl_xor_sync(0x000000FFu, mx, o));
            sm += __shfl_xor_sync(0x000000FFu, sm, o);
        }
        if (t == 0) {
            g_d[bc] = mx;
            g_e[bc] = sm * (1.0f / HW);
        }
    }
}

// ---------------------------------------------------------------------------
// Kernel 2: row sums. grid (32 batches, 4 row-chunks) x 128 threads.
// Thread owns row i; loops j over smem (broadcast LDS.64).
// s_i = sum_j exp(d_i d_j + e_i e_j);   a_i = d_i/s_i, b_i = e_i/s_i
// ---------------------------------------------------------------------------
__global__ void rowsum_kernel() {
    __shared__ float2 de[CH];
    const int b = blockIdx.x;
    const int t = threadIdx.x;

    for (int k = t; k < CH; k += 128)
        de[k] = make_float2(g_d[b * CH + k], g_e[b * CH + k]);
    __syncthreads();

    const int i  = blockIdx.y * 128 + t;
    const float di = de[i].x;
    const float ei = de[i].y;

    float s = 0.0f;
#pragma unroll 8
    for (int j = 0; j < CH; ++j) {
        float2 v = de[j];
        s += __expf(fmaf(di, v.x, ei * v.y));
    }
    const float inv = 1.0f / s;
    g_ab[b * CH + i] = make_float2(di * inv, ei * inv);
}

// ---------------------------------------------------------------------------
// Kernel 3: column sums -> f. grid (32, 4) x 128. Thread owns column j.
// f_max[j] = sum_i a_i * exp(l_ij), f_mean[j] = sum_i b_i * exp(l_ij)
// (l_ij symmetric so recompute with (d_j,e_j) against (d_i,e_i)).
// ---------------------------------------------------------------------------
__global__ void colsum_kernel(const float* __restrict__ alpha,
                              const float* __restrict__ beta) {
    __shared__ float4 s4[CH];   // (d_i, e_i, a_i, b_i)
    const int b = blockIdx.x;
    const int t = threadIdx.x;

    for (int k = t; k < CH; k += 128) {
        float2 ab = g_ab[b * CH + k];
        s4[k] = make_float4(g_d[b * CH + k], g_e[b * CH + k], ab.x, ab.y);
    }
    __syncthreads();

    const int j  = blockIdx.y * 128 + t;
    const float dj = s4[j].x;
    const float ej = s4[j].y;

    float fm = 0.0f, fe = 0.0f;
#pragma unroll 8
    for (int i = 0; i < CH; ++i) {
        float4 v = s4[i];
        float E = __expf(fmaf(dj, v.x, ej * v.y));
        fm = fmaf(v.z, E, fm);
        fe = fmaf(v.w, E, fe);
    }
    g_f[b * CH + j] = alpha[0] * fm + beta[0] * fe;
}

// ---------------------------------------------------------------------------
// Kernel 4: broadcast f[b,c] over HW. One block of 256 threads per (b,c);
// each thread stores 4 x float4 (STG.128).
// ---------------------------------------------------------------------------
__global__ void bcast_kernel(float4* __restrict__ out) {
    const int bc = blockIdx.x;
    const float v = g_f[bc];
    const float4 vv = make_float4(v, v, v, v);
    float4* p = out + (size_t)bc * (HW / 4);
    const int t = threadIdx.x;
#pragma unroll
    for (int k = 0; k < 4; ++k)
        p[t + k * 256] = vv;
}

// ---------------------------------------------------------------------------
extern "C" void kernel_launch(void* const* d_in, const int* in_sizes, int n_in,
                              void* d_out, int out_size) {
    const float* x     = (const float*)d_in[0];
    const float* alpha = (const float*)d_in[1];
    const float* beta  = (const float*)d_in[2];
    float* out = (float*)d_out;

    pool_kernel<<<BC, 256>>>((const float4*)x);
    rowsum_kernel<<<dim3(BATCH, 4), 128>>>();
    colsum_kernel<<<dim3(BATCH, 4), 128>>>(alpha, beta);
    bcast_kernel<<<BC, 256>>>((float4*)out);
}

// round 2
// speedup vs baseline: 1.0130x; 1.0130x over previous
#include <cuda_runtime.h>
#include <cuda_bf16.h>

// B=32, C=512, H=W=64
//   d[b,c]=max_HW x, e[b,c]=mean_HW x
//   y = softmax_j(d_i d_j + e_i e_j); f_j = alpha*sum_i d_i y_ij + beta*sum_i e_i y_ij
//   out[b,c,:,:] = f[b,c]
//
// 3 kernels:
//   pool     : read 268 MB, per-(b,c) max+mean                     (HBM read bound)
//   rowsum   : s_i = sum_j exp(l_ij); pack (d,e, a*d/s, b*e/s)     (tiny)
//   bcastcol : warp0 computes f[b,c] (column sum via symmetry),
//              block broadcasts over 4096 elems                    (HBM write bound,
//              colsum hidden under other blocks' stores)
// No max-subtract needed: |logit| <= d_max^2 ~ 18 << 88.

#define BATCH 32
#define CH    512
#define HW    4096
#define BC    (BATCH * CH)

__device__ float  g_d[BC];
__device__ float  g_e[BC];
__device__ float4 g_pack[BC];   // (d_i, e_i, alpha*d_i/s_i, beta*e_i/s_i)

// ---------------------------------------------------------------------------
// Kernel 1: per-(b,c) max + mean over 4096 contiguous floats.
// One block of 256 threads per (b,c); each thread streams 4 x float4.
// ---------------------------------------------------------------------------
__global__ void pool_kernel(const float4* __restrict__ x) {
    const int bc = blockIdx.x;
    const float4* p = x + (size_t)bc * (HW / 4);
    const int t = threadIdx.x;

    float mx0 = -3.402823466e38f, mx1 = mx0;
    float sm0 = 0.0f, sm1 = 0.0f;
    float4 v0 = __ldcs(p + t);
    float4 v1 = __ldcs(p + t + 256);
    float4 v2 = __ldcs(p + t + 512);
    float4 v3 = __ldcs(p + t + 768);
    mx0 = fmaxf(fmaxf(v0.x, v0.y), fmaxf(v0.z, v0.w));
    mx1 = fmaxf(fmaxf(v1.x, v1.y), fmaxf(v1.z, v1.w));
    mx0 = fmaxf(mx0, fmaxf(fmaxf(v2.x, v2.y), fmaxf(v2.z, v2.w)));
    mx1 = fmaxf(mx1, fmaxf(fmaxf(v3.x, v3.y), fmaxf(v3.z, v3.w)));
    sm0 = (v0.x + v0.y) + (v0.z + v0.w) + ((v2.x + v2.y) + (v2.z + v2.w));
    sm1 = (v1.x + v1.y) + (v1.z + v1.w) + ((v3.x + v3.y) + (v3.z + v3.w));
    float mx = fmaxf(mx0, mx1);
    float sm = sm0 + sm1;

#pragma unroll
    for (int o = 16; o > 0; o >>= 1) {
        mx = fmaxf(mx, __shfl_xor_sync(0xFFFFFFFFu, mx, o));
        sm += __shfl_xor_sync(0xFFFFFFFFu, sm, o);
    }
    __shared__ float smx[8];
    __shared__ float ssm[8];
    const int w = t >> 5;
    if ((t & 31) == 0) { smx[w] = mx; ssm[w] = sm; }
    __syncthreads();
    if (t < 8) {
        mx = smx[t];
        sm = ssm[t];
#pragma unroll
        for (int o = 4; o > 0; o >>= 1) {
            mx = fmaxf(mx, __shfl_xor_sync(0x000000FFu, mx, o));
            sm += __shfl_xor_sync(0x000000FFu, sm, o);
        }
        if (t == 0) {
            g_d[bc] = mx;
            g_e[bc] = sm * (1.0f / HW);
        }
    }
}

// ---------------------------------------------------------------------------
// Kernel 2: row sums + pack. grid (32 batches, 4 row-chunks) x 128 threads.
// Thread owns row i; loops j over smem (broadcast LDS.64).
// Packs alpha/beta into the weights so the fused kernel needs no scalars.
// ---------------------------------------------------------------------------
__global__ void rowsum_kernel(const float* __restrict__ alpha,
                              const float* __restrict__ beta) {
    __shared__ float2 de[CH];
    const int b = blockIdx.x;
    const int t = threadIdx.x;

    for (int k = t; k < CH; k += 128)
        de[k] = make_float2(g_d[b * CH + k], g_e[b * CH + k]);
    __syncthreads();

    const int i  = blockIdx.y * 128 + t;
    const float di = de[i].x;
    const float ei = de[i].y;

    float s = 0.0f;
#pragma unroll 8
    for (int j = 0; j < CH; ++j) {
        float2 v = de[j];
        s += __expf(fmaf(di, v.x, ei * v.y));
    }
    const float inv = 1.0f / s;
    g_pack[b * CH + i] = make_float4(di, ei, alpha[0] * di * inv,
                                             beta[0]  * ei * inv);
}

// ---------------------------------------------------------------------------
// Kernel 3: fused column-sum + broadcast. One block of 256 threads per (b,c).
// Warp 0 computes f[b,c] = sum_i (a'_i + via e) exp(l_ij) via symmetry;
// then all threads store 4 x STG.128 (streaming).
// ---------------------------------------------------------------------------
__global__ void bcast_fused_kernel(float4* __restrict__ out) {
    const int bc = blockIdx.x;
    const int b  = bc >> 9;
    const int t  = threadIdx.x;

    __shared__ float sf;
    if (t < 32) {
        const float4 me = g_pack[bc];       // dj, ej in .x, .y
        const float dj = me.x;
        const float ej = me.y;
        float fm = 0.0f, fe = 0.0f;
#pragma unroll
        for (int k = 0; k < CH / 32; ++k) {
            float4 p = g_pack[b * CH + k * 32 + t];
            float E = __expf(fmaf(dj, p.x, ej * p.y));
            fm = fmaf(p.z, E, fm);
            fe = fmaf(p.w, E, fe);
        }
        float f = fm + fe;
#pragma unroll
        for (int o = 16; o > 0; o >>= 1)
            f += __shfl_xor_sync(0xFFFFFFFFu, f, o);
        if (t == 0) sf = f;
    }
    __syncthreads();

    const float v = sf;
    const float4 vv = make_float4(v, v, v, v);
    float4* p = out + (size_t)bc * (HW / 4);
    __stcs(p + t,       vv);
    __stcs(p + t + 256, vv);
    __stcs(p + t + 512, vv);
    __stcs(p + t + 768, vv);
}

// ---------------------------------------------------------------------------
extern "C" void kernel_launch(void* const* d_in, const int* in_sizes, int n_in,
                              void* d_out, int out_size) {
    const float* x     = (const float*)d_in[0];
    const float* alpha = (const float*)d_in[1];
    const float* beta  = (const float*)d_in[2];
    float* out = (float*)d_out;

    pool_kernel<<<BC, 256>>>((const float4*)x);
    rowsum_kernel<<<dim3(BATCH, 4), 128>>>(alpha, beta);
    bcast_fused_kernel<<<BC, 256>>>((float4*)out);
}